// round 17
// baseline (speedup 1.0000x reference)
#include <cuda_runtime.h>
#include <cuda_fp16.h>
#include <cstdint>

#define SEQ    8192
#define D_IN   4096
#define D_OUT  4096
#define RANK   16
#define NADP   8

// ---- tile config -----------------------------------------------------------
#define BM 128
#define BN 256
#define BK 64                        // fp16 elements per k-chunk (128B rows)
#define NCHUNK (D_IN / BK)           // 64
#define KSTEPS 4                     // 4 x k16 per chunk
#define STAGES 3
#define THREADS 512

#define A_BYTES (BM * BK * 2)        // 16384
#define B_BYTES (BN * BK * 2)        // 32768
#define OFF_A 0
#define OFF_B A_BYTES
#define STAGE_BYTES (A_BYTES + B_BYTES)      // 49152
#define MAIN_BYTES  (STAGES * STAGE_BYTES)   // 147456

// epilogue: adapters 0..6 reuse the pipeline region post-loop (stride 20 + 4 skew)
#define COL_STRIDE 20
#define ADP_STRIDE (BN * COL_STRIDE + 4)     // 5124 floats
// dedicated region (float indices), staged in prologue
#define A7_OFF   28                          // bank 28 = 4*7, continues skew pattern
#define AOUT_OFF (A7_OFF + BN * COL_STRIDE)  // 28 + 5120 = 5148  (FIX: was BN*RANK)
#define BIAS_OFF (AOUT_OFF + BM * RANK)      // + 2048
#define TOK_OFF  (BIAS_OFF + BN)             // + 256
#define DED_FLOATS (TOK_OFF + BM)            // + 128
#define SMEM_TOTAL (MAIN_BYTES + DED_FLOATS * 4)

// ---- device scratch --------------------------------------------------------
__device__ float  g_aout[SEQ * RANK];
__device__ __half g_xh[(size_t)SEQ * D_IN];
__device__ __half g_wh[(size_t)D_OUT * D_IN];   // transposed: [N][K]

// ---- PTX helpers -----------------------------------------------------------
__device__ __forceinline__ uint32_t smem_u32(const void* p) {
    uint32_t a;
    asm("{ .reg .u64 t; cvta.to.shared.u64 t, %1; cvt.u32.u64 %0, t; }"
        : "=r"(a) : "l"(p));
    return a;
}
// 128B-row swizzle: 16B-chunk ^= (row & 7)
#define SWZ128(o) ((o) ^ (((o) >> 3) & 0x70))

#define CP16(dst, src) \
    asm volatile("cp.async.cg.shared.global [%0], [%1], 16;" \
                 :: "r"(dst), "l"(src))
#define CP_COMMIT() asm volatile("cp.async.commit_group;" ::: "memory")
#define CP_WAIT1()  asm volatile("cp.async.wait_group 1;" ::: "memory")
#define CP_WAIT0()  asm volatile("cp.async.wait_group 0;" ::: "memory")

__device__ __forceinline__ void ldsm4(uint32_t* r, uint32_t addr) {
    asm volatile("ldmatrix.sync.aligned.m8n8.x4.shared.b16 {%0,%1,%2,%3}, [%4];"
                 : "=r"(r[0]), "=r"(r[1]), "=r"(r[2]), "=r"(r[3]) : "r"(addr));
}
__device__ __forceinline__ void mma_f16(float* d, const uint32_t* a,
                                        const uint32_t* b) {
    asm volatile(
        "mma.sync.aligned.m16n8k16.row.col.f32.f16.f16.f32 "
        "{%0,%1,%2,%3}, {%4,%5,%6,%7}, {%8,%9}, {%0,%1,%2,%3};"
        : "+f"(d[0]), "+f"(d[1]), "+f"(d[2]), "+f"(d[3])
        : "r"(a[0]), "r"(a[1]), "r"(a[2]), "r"(a[3]), "r"(b[0]), "r"(b[1]));
}

// ---------------------------------------------------------------------------
// W prepass: transpose + fp16 convert:  W[k][n] fp32 -> g_wh[n][k]
// ---------------------------------------------------------------------------
__global__ void convert_w_kernel(const float* __restrict__ W)
{
    __shared__ float t[32][33];
    const int n0 = blockIdx.x * 32, k0 = blockIdx.y * 32;
    const int tx = threadIdx.x, ty = threadIdx.y;   // 32 x 8
#pragma unroll
    for (int i = 0; i < 32; i += 8)
        t[ty + i][tx] = W[(size_t)(k0 + ty + i) * D_OUT + n0 + tx];
    __syncthreads();
#pragma unroll
    for (int i = 0; i < 32; i += 8) {
        const float v = t[tx][ty + i];              // = W[k0+tx][n0+ty+i]
        g_wh[(size_t)(n0 + ty + i) * D_IN + k0 + tx] = __float2half_rn(v);
    }
}

// ---------------------------------------------------------------------------
// Fused: a_out = (x @ A[e]^T) * scaling  AND  x -> fp16.
// One block per token row, 128 threads; x read exactly once.
// ---------------------------------------------------------------------------
__global__ void lora_a_convert_kernel(const float* __restrict__ x,
                                      const float* __restrict__ A,
                                      const float* __restrict__ scalings,
                                      const int*   __restrict__ tok)
{
    const int s = blockIdx.x;
    const int t = threadIdx.x;
    const int e = tok[s];
    const float* xr = x + (size_t)s * D_IN;
    const float* Ae = A + (size_t)e * RANK * D_IN;

    float acc[RANK];
#pragma unroll
    for (int r = 0; r < RANK; ++r) acc[r] = 0.f;

#pragma unroll
    for (int it = 0; it < 8; ++it) {
        const int k = t * 4 + it * 512;
        const float4 v = *(const float4*)(xr + k);

        // fp16 convert (hidden under the dot-product FMAs)
        const size_t o = (size_t)s * D_IN + k;
        *(__half2*)(g_xh + o)     = __floats2half2_rn(v.x, v.y);
        *(__half2*)(g_xh + o + 2) = __floats2half2_rn(v.z, v.w);

#pragma unroll
        for (int r = 0; r < RANK; ++r) {
            const float4 av = *(const float4*)(Ae + r * D_IN + k);
            acc[r] += v.x * av.x + v.y * av.y + v.z * av.z + v.w * av.w;
        }
    }
#pragma unroll
    for (int r = 0; r < RANK; ++r) {
#pragma unroll
        for (int o = 16; o > 0; o >>= 1)
            acc[r] += __shfl_xor_sync(0xffffffffu, acc[r], o);
    }
    __shared__ float red[4][RANK];
    const int warp = t >> 5, lane = t & 31;
    if (lane == 0) {
#pragma unroll
        for (int r = 0; r < RANK; ++r) red[warp][r] = acc[r];
    }
    __syncthreads();
    if (t < RANK) {
        const float v = red[0][t] + red[1][t] + red[2][t] + red[3][t];
        g_aout[s * RANK + t] = v * scalings[s];
    }
}

// ---------------------------------------------------------------------------
// Main fused fp16 HMMA GEMM:  out = x @ W + bias + aout@B[e]^T
// 128x256 tile, BK=64, 512 threads (16 warps, warp tile 32x64),
// 3-stage cp.async pipeline, ONE __syncthreads per chunk.
// ---------------------------------------------------------------------------
__device__ __forceinline__ void load_stage(uint32_t st, int kc, int m0, int n0,
                                           int tid)
{
    const int k0 = kc * BK;
#pragma unroll
    for (int i = tid; i < BM * 8; i += THREADS) {   // 1024 16B-chunks (A)
        const int row = i >> 3, c = i & 7;
        const uint32_t sw = SWZ128((uint32_t)(row * 128 + c * 16));
        CP16(st + OFF_A + sw,
             (const char*)(g_xh + (size_t)(m0 + row) * D_IN + k0 + c * 8));
    }
#pragma unroll
    for (int i = tid; i < BN * 8; i += THREADS) {   // 2048 16B-chunks (B)
        const int row = i >> 3, c = i & 7;
        const uint32_t sw = SWZ128((uint32_t)(row * 128 + c * 16));
        CP16(st + OFF_B + sw,
             (const char*)(g_wh + (size_t)(n0 + row) * D_IN + k0 + c * 8));
    }
}

__global__ __launch_bounds__(THREADS, 1)
void fused_mma_kernel(const float* __restrict__ bias,
                      const float* __restrict__ Bbuf,
                      const int*   __restrict__ tok,
                      float*       __restrict__ out)
{
    extern __shared__ __align__(1024) char smem[];
    const uint32_t sb = smem_u32(smem);
    const int tid  = threadIdx.x;
    const int lane = tid & 31;
    const int wid  = tid >> 5;
    const int wm   = wid >> 2;          // 0..3 -> m offset wm*32
    const int wn   = wid & 3;           // 0..3 -> n offset wn*64
    const int m0 = blockIdx.y * BM;
    const int n0 = blockIdx.x * BN;

    // swizzled lane offsets (ks=0); ks XORs bits 5-6 (32B steps) post-swizzle
    uint32_t aswz[2], bswz[4];
#pragma unroll
    for (int mt = 0; mt < 2; ++mt)
        aswz[mt] = SWZ128((uint32_t)((wm * 32 + mt * 16 + (lane & 15)) * 128
                                     + ((lane >> 4) & 1) * 16));
#pragma unroll
    for (int ntp = 0; ntp < 4; ++ntp)
        bswz[ntp] = SWZ128((uint32_t)((wn * 64 + ntp * 16 + ((lane >> 4) & 1) * 8
                                       + (lane & 7)) * 128
                                      + ((lane >> 3) & 1) * 16));

    float acc[2][8][4];
#pragma unroll
    for (int mt = 0; mt < 2; ++mt)
#pragma unroll
        for (int nt = 0; nt < 8; ++nt)
#pragma unroll
            for (int q = 0; q < 4; ++q) acc[mt][nt][q] = 0.f;

    // prologue: fill stages 0..1
    load_stage(sb + 0 * STAGE_BYTES, 0, m0, n0, tid); CP_COMMIT();
    load_stage(sb + 1 * STAGE_BYTES, 1, m0, n0, tid); CP_COMMIT();

    // stage dedicated epilogue data (adapter 7 slab, aout, bias, tokens)
    float* ef = (float*)(smem + MAIN_BYTES);
    float* sfmain = (float*)smem;
    int* stok = (int*)(ef + TOK_OFF);
    for (int i = tid; i < BN * 4; i += THREADS) {         // adapter 7: 1024 f4
        const int c = i >> 2, q = i & 3;
        const float4 v = ((const float4*)(Bbuf + ((size_t)7 * D_OUT + n0 + c) * RANK))[q];
        *(float4*)(ef + A7_OFF + c * COL_STRIDE + q * 4) = v;
    }
    for (int i = tid; i < BM * RANK / 4; i += THREADS)
        ((float4*)(ef + AOUT_OFF))[i] =
            ((const float4*)(g_aout + (size_t)m0 * RANK))[i];
    for (int i = tid; i < BN / 4; i += THREADS)
        ((float4*)(ef + BIAS_OFF))[i] = ((const float4*)(bias + n0))[i];
    if (tid < BM) stok[tid] = tok[m0 + tid];

    for (int ci = 0; ci < NCHUNK; ++ci) {
        if (ci + 1 < NCHUNK) { CP_WAIT1(); } else { CP_WAIT0(); }
        __syncthreads();   // data(ci) visible; stage (ci-1)%3 fully consumed

        if (ci + 2 < NCHUNK) {
            load_stage(sb + (uint32_t)((ci + 2) % 3) * STAGE_BYTES,
                       ci + 2, m0, n0, tid);
            CP_COMMIT();
        }

        const uint32_t st = sb + (uint32_t)(ci % 3) * STAGE_BYTES;
#pragma unroll
        for (int ks = 0; ks < KSTEPS; ++ks) {
            const uint32_t kx = (uint32_t)ks << 5;
            uint32_t af[2][4], bf[8][2];
#pragma unroll
            for (int mt = 0; mt < 2; ++mt)
                ldsm4(af[mt], st + OFF_A + (aswz[mt] ^ kx));
#pragma unroll
            for (int ntp = 0; ntp < 4; ++ntp) {
                uint32_t t4[4];
                ldsm4(t4, st + OFF_B + (bswz[ntp] ^ kx));
                bf[2 * ntp][0] = t4[0]; bf[2 * ntp][1] = t4[1];
                bf[2 * ntp + 1][0] = t4[2]; bf[2 * ntp + 1][1] = t4[3];
            }
#pragma unroll
            for (int mt = 0; mt < 2; ++mt)
#pragma unroll
                for (int nt = 0; nt < 8; ++nt)
                    mma_f16(acc[mt][nt], af[mt], bf[nt]);
        }
    }

    // ---- stage adapters 0..6 into the freed pipeline region ---------------
    __syncthreads();                                  // all MMA consumption done
    for (int i = tid; i < 7 * BN * 4; i += THREADS) {     // 7168 float4s
        const int e = i >> 10, rem = i & 1023, c = rem >> 2, q = rem & 3;
        const float4 v = ((const float4*)(Bbuf + ((size_t)e * D_OUT + n0 + c) * RANK))[q];
        *(float4*)(sfmain + e * ADP_STRIDE + c * COL_STRIDE + q * 4) = v;
    }
    __syncthreads();

    // ---- combine + store --------------------------------------------------
#pragma unroll
    for (int rr = 0; rr < 4; ++rr) {
        const int mt = rr >> 1, half = rr & 1;
        const int r = wm * 32 + mt * 16 + half * 8 + (lane >> 2);
        const int e = stok[r];
        const float* ar = ef + AOUT_OFF + r * RANK;
        const float4 a0 = *(const float4*)(ar + 0);
        const float4 a1 = *(const float4*)(ar + 4);
        const float4 a2 = *(const float4*)(ar + 8);
        const float4 a3 = *(const float4*)(ar + 12);
        const float* Be = (e < 7) ? (sfmain + e * ADP_STRIDE) : (ef + A7_OFF);
        float* outp = out + (size_t)(m0 + r) * D_OUT + n0;
#pragma unroll
        for (int nt = 0; nt < 8; ++nt) {
            const int col0 = wn * 64 + nt * 8 + 2 * (lane & 3);
            float v2[2];
#pragma unroll
            for (int c = 0; c < 2; ++c) {
                const int col = col0 + c;
                const float* bp = Be + col * COL_STRIDE;
                const float4 b0 = *(const float4*)(bp + 0);
                const float4 b1 = *(const float4*)(bp + 4);
                const float4 b2 = *(const float4*)(bp + 8);
                const float4 b3 = *(const float4*)(bp + 12);
                float d = acc[mt][nt][half * 2 + c] + ef[BIAS_OFF + col];
                d += a0.x * b0.x + a0.y * b0.y + a0.z * b0.z + a0.w * b0.w;
                d += a1.x * b1.x + a1.y * b1.y + a1.z * b1.z + a1.w * b1.w;
                d += a2.x * b2.x + a2.y * b2.y + a2.z * b2.z + a2.w * b2.w;
                d += a3.x * b3.x + a3.y * b3.y + a3.z * b3.z + a3.w * b3.w;
                v2[c] = d;
            }
            *(float2*)(outp + col0) = make_float2(v2[0], v2[1]);
        }
    }
}

// ---------------------------------------------------------------------------
extern "C" void kernel_launch(void* const* d_in, const int* in_sizes, int n_in,
                              void* d_out, int out_size)
{
    const float* x    = (const float*)d_in[0];
    const float* W    = (const float*)d_in[1];
    const float* bias = (const float*)d_in[2];
    const float* A    = (const float*)d_in[3];
    const float* B    = (const float*)d_in[4];
    const float* scal = (const float*)d_in[5];
    const int*   tok  = (const int*)d_in[6];
    float* out = (float*)d_out;

    static int smem_set = 0;
    if (!smem_set) {
        cudaFuncSetAttribute(fused_mma_kernel,
                             cudaFuncAttributeMaxDynamicSharedMemorySize,
                             SMEM_TOTAL);
        smem_set = 1;
    }

    convert_w_kernel<<<dim3(D_OUT / 32, D_IN / 32), dim3(32, 8)>>>(W);
    lora_a_convert_kernel<<<SEQ, 128>>>(x, A, scal, tok);
    fused_mma_kernel<<<dim3(D_OUT / BN, SEQ / BM), THREADS, SMEM_TOTAL>>>(bias, B, tok, out);
}